// round 1
// baseline (speedup 1.0000x reference)
#include <cuda_runtime.h>
#include <math.h>

#define NN 50000
#define NEDGE 800000
#define ETOT (NEDGE + NN)
#define F 128

// ---- scratch (static device globals; no allocation anywhere) ----
__device__ float g_h[(size_t)NN * F];     // per-layer transformed features
__device__ float g_x2[(size_t)NN * F];    // layer-2 input
__device__ float g_acc[(size_t)NN * F];   // aggregation accumulator
__device__ float g_as[NN * 8];            // alpha_src per node/head
__device__ float g_ad[NN * 8];            // alpha_dst per node/head
__device__ float g_m[NN * 8];             // segment max
__device__ float g_s[NN * 8];             // segment sum -> reciprocal
__device__ float g_w[(size_t)ETOT * 8];   // exp weights per edge/head

__device__ __forceinline__ float lrelu(float v) { return v >= 0.f ? v : 0.2f * v; }

__device__ __forceinline__ void atomicMaxF(float* a, float v) {
    if (v >= 0.f) atomicMax((int*)a, __float_as_int(v));
    else          atomicMin((unsigned int*)a, __float_as_uint(v));
}

// ---- GEMM h = x @ W, fused alpha_src/alpha_dst epilogue ----
// block = 256 threads (8 warps), 32 rows/block, 4 rows/warp, 4 cols/lane
__global__ void gemm_alpha(const float* __restrict__ xin, int use_x2,
                           const float* __restrict__ W,
                           const float* __restrict__ asr,
                           const float* __restrict__ adr)
{
    const float* x = use_x2 ? g_x2 : xin;
    __shared__ float Wsh[64 * 128];   // 32 KB
    __shared__ float Xsh[32 * 64];    // 8 KB
    int tid  = threadIdx.x;
    int warp = tid >> 5, lane = tid & 31;
    int row0 = blockIdx.x * 32;
    float acc[4][4];
#pragma unroll
    for (int r = 0; r < 4; r++)
#pragma unroll
        for (int c = 0; c < 4; c++) acc[r][c] = 0.f;

    for (int kb = 0; kb < 128; kb += 64) {
        for (int i = tid; i < 2048; i += 256)
            ((float4*)Wsh)[i] = ((const float4*)(W + kb * 128))[i];
        for (int i = tid; i < 512; i += 256) {
            int r = i >> 4, c4 = i & 15;
            int row = row0 + r;
            float4 v = make_float4(0.f, 0.f, 0.f, 0.f);
            if (row < NN) v = *(const float4*)(x + (size_t)row * 128 + kb + c4 * 4);
            ((float4*)Xsh)[i] = v;
        }
        __syncthreads();
#pragma unroll 8
        for (int k = 0; k < 64; k++) {
            float4 wv = ((float4*)Wsh)[k * 32 + lane];
#pragma unroll
            for (int r = 0; r < 4; r++) {
                float xv = Xsh[(warp * 4 + r) * 64 + k];
                acc[r][0] = fmaf(xv, wv.x, acc[r][0]);
                acc[r][1] = fmaf(xv, wv.y, acc[r][1]);
                acc[r][2] = fmaf(xv, wv.z, acc[r][2]);
                acc[r][3] = fmaf(xv, wv.w, acc[r][3]);
            }
        }
        __syncthreads();
    }

    // epilogue: write h, compute alpha_s/alpha_d (per head = 4-lane group reduce)
    float4 a_s = ((const float4*)asr)[lane];
    float4 a_d = ((const float4*)adr)[lane];
#pragma unroll
    for (int r = 0; r < 4; r++) {
        int row = row0 + warp * 4 + r;
        if (row >= NN) continue;
        float4 v = make_float4(acc[r][0], acc[r][1], acc[r][2], acc[r][3]);
        ((float4*)(g_h + (size_t)row * 128))[lane] = v;
        float ps = v.x * a_s.x + v.y * a_s.y + v.z * a_s.z + v.w * a_s.w;
        float pd = v.x * a_d.x + v.y * a_d.y + v.z * a_d.z + v.w * a_d.w;
        ps += __shfl_down_sync(0xffffffffu, ps, 2);
        ps += __shfl_down_sync(0xffffffffu, ps, 1);
        pd += __shfl_down_sync(0xffffffffu, pd, 2);
        pd += __shfl_down_sync(0xffffffffu, pd, 1);
        if ((lane & 3) == 0) {
            g_as[row * 8 + (lane >> 2)] = ps;
            g_ad[row * 8 + (lane >> 2)] = pd;
        }
    }
}

__global__ void init_seg() {
    int i = blockIdx.x * blockDim.x + threadIdx.x;
    if (i < NN * 8) { g_m[i] = -INFINITY; g_s[i] = 0.f; }
}

__global__ void zero_acc() {
    int i = blockIdx.x * blockDim.x + threadIdx.x;
    if (i < NN * F / 4)
        ((float4*)g_acc)[i] = make_float4(0.f, 0.f, 0.f, 0.f);
}

__global__ void edge_max(const int* __restrict__ ei) {
    int e = blockIdx.x * blockDim.x + threadIdx.x;
    if (e >= ETOT) return;
    int s, d;
    if (e < NEDGE) { s = ei[e]; d = ei[NEDGE + e]; } else { s = e - NEDGE; d = s; }
    const float4* as4 = (const float4*)(g_as + s * 8);
    const float4* ad4 = (const float4*)(g_ad + d * 8);
    float* m = g_m + d * 8;
#pragma unroll
    for (int q = 0; q < 2; q++) {
        float4 a = as4[q], b = ad4[q];
        atomicMaxF(m + q * 4 + 0, lrelu(a.x + b.x));
        atomicMaxF(m + q * 4 + 1, lrelu(a.y + b.y));
        atomicMaxF(m + q * 4 + 2, lrelu(a.z + b.z));
        atomicMaxF(m + q * 4 + 3, lrelu(a.w + b.w));
    }
}

__global__ void edge_exp(const int* __restrict__ ei) {
    int e = blockIdx.x * blockDim.x + threadIdx.x;
    if (e >= ETOT) return;
    int s, d;
    if (e < NEDGE) { s = ei[e]; d = ei[NEDGE + e]; } else { s = e - NEDGE; d = s; }
    const float4* as4 = (const float4*)(g_as + s * 8);
    const float4* ad4 = (const float4*)(g_ad + d * 8);
    const float4* m4  = (const float4*)(g_m + d * 8);
    float* sacc = g_s + d * 8;
    float4* wp = (float4*)(g_w + (size_t)e * 8);
#pragma unroll
    for (int q = 0; q < 2; q++) {
        float4 a = as4[q], b = ad4[q], m = m4[q];
        float w0 = __expf(lrelu(a.x + b.x) - m.x);
        float w1 = __expf(lrelu(a.y + b.y) - m.y);
        float w2 = __expf(lrelu(a.z + b.z) - m.z);
        float w3 = __expf(lrelu(a.w + b.w) - m.w);
        atomicAdd(sacc + q * 4 + 0, w0);
        atomicAdd(sacc + q * 4 + 1, w1);
        atomicAdd(sacc + q * 4 + 2, w2);
        atomicAdd(sacc + q * 4 + 3, w3);
        wp[q] = make_float4(w0, w1, w2, w3);
    }
}

__global__ void inv_s() {
    int i = blockIdx.x * blockDim.x + threadIdx.x;
    if (i < NN * 8) g_s[i] = 1.f / (g_s[i] + 1e-16f);
}

// ---- warp-per-edge aggregation: lane owns 4 channels; vectorized RED ----
__global__ void aggregate(const int* __restrict__ ei) {
    int gw   = (int)((blockIdx.x * (size_t)blockDim.x + threadIdx.x) >> 5);
    int lane = threadIdx.x & 31;
    if (gw >= ETOT) return;
    int s, d;
    if (gw < NEDGE) { s = ei[gw]; d = ei[NEDGE + gw]; } else { s = gw - NEDGE; d = s; }
    int head = lane >> 2;
    float w = g_w[(size_t)gw * 8 + head] * g_s[d * 8 + head];
    float4 hv = ((const float4*)(g_h + (size_t)s * 128))[lane];
    float4 v = make_float4(hv.x * w, hv.y * w, hv.z * w, hv.w * w);
    float* out = g_acc + (size_t)d * 128 + lane * 4;
    asm volatile("red.global.add.v4.f32 [%0], {%1,%2,%3,%4};"
                 :: "l"(out), "f"(v.x), "f"(v.y), "f"(v.z), "f"(v.w)
                 : "memory");
}

__global__ void bias_act(const float* __restrict__ bias, float* __restrict__ out, int to_x2) {
    int i = blockIdx.x * blockDim.x + threadIdx.x;
    if (i >= NN * F) return;
    float v = g_acc[i] + bias[i & 127];
    v = v > 0.f ? v : expm1f(v);
    if (to_x2) g_x2[i] = v;
    else       out[i] = v;
}

extern "C" void kernel_launch(void* const* d_in, const int* in_sizes, int n_in,
                              void* d_out, int out_size) {
    const float* x   = (const float*)d_in[0];
    const int*   ei  = (const int*)d_in[1];
    const float* W1  = (const float*)d_in[2];
    const float* as1 = (const float*)d_in[3];
    const float* ad1 = (const float*)d_in[4];
    const float* b1  = (const float*)d_in[5];
    const float* W2  = (const float*)d_in[6];
    const float* as2 = (const float*)d_in[7];
    const float* ad2 = (const float*)d_in[8];
    const float* b2  = (const float*)d_in[9];
    float* out = (float*)d_out;

    const int GB   = (NN + 31) / 32;
    const int EB   = (ETOT + 255) / 256;
    const int NB8  = (NN * 8 + 255) / 256;
    const int NBF  = (NN * F + 255) / 256;
    const int NBF4 = (NN * F / 4 + 255) / 256;
    const int AGB  = (int)(((size_t)ETOT * 32 + 255) / 256);

    for (int layer = 0; layer < 2; layer++) {
        gemm_alpha<<<GB, 256>>>(x, layer,
                                layer ? W2 : W1,
                                layer ? as2 : as1,
                                layer ? ad2 : ad1);
        init_seg<<<NB8, 256>>>();
        zero_acc<<<NBF4, 256>>>();
        edge_max<<<EB, 256>>>(ei);
        edge_exp<<<EB, 256>>>(ei);
        inv_s<<<NB8, 256>>>();
        aggregate<<<AGB, 256>>>(ei);
        bias_act<<<NBF, 256>>>(layer ? b2 : b1, out, layer == 0);
    }
}